// round 9
// baseline (speedup 1.0000x reference)
#include <cuda_runtime.h>

// Per-frame precomputed matrices: M[f] = initial_extrinsics[f] @ inv(c2w[f]).
// Row 3 of M is EXACTLY (0,0,0,1) for every frame (both factors have bottom
// row e4), so only rows 0..2 are ever read back. Stride kept at 4 float4
// (64 B) so each entry stays line-aligned (rows 0-2 live in 2 sectors).
#define NF_MAX 10000
__device__ __align__(128) float4 g_M[NF_MAX * 4];

// ---------------------------------------------------------------------------
// Phase 1: per-frame precompute, all fp32, 64-thread blocks.
// ---------------------------------------------------------------------------
__global__ void precompute_kernel(const float* __restrict__ r,
                                  const float* __restrict__ t,
                                  const float* __restrict__ E,
                                  int nf) {
    int f = blockIdx.x * blockDim.x + threadIdx.x;
    if (f >= nf) return;

    float v0 = r[3 * f + 0];
    float v1 = r[3 * f + 1];
    float v2 = r[3 * f + 2];

    float n = sqrtf(v0 * v0 + v1 * v1 + v2 * v2) + 1e-15f;
    float sn, cn;
    __sincosf(n, &sn, &cn);
    float a = sn / n;
    float b = (1.0f - cn) / (n * n);

    // Reference vec2skew (transpose of standard skew):
    float S[3][3] = {{0.0f,  v2, -v1},
                     {-v2, 0.0f,  v0},
                     { v1, -v0, 0.0f}};

    float S2[3][3];
#pragma unroll
    for (int i = 0; i < 3; i++)
#pragma unroll
        for (int j = 0; j < 3; j++)
            S2[i][j] = S[i][0] * S[0][j] + S[i][1] * S[1][j] + S[i][2] * S[2][j];

    float R[3][3];
#pragma unroll
    for (int i = 0; i < 3; i++)
#pragma unroll
        for (int j = 0; j < 3; j++)
            R[i][j] = (i == j ? 1.0f : 0.0f) + a * S[i][j] + b * S2[i][j];

    // rigid inverse of c2w
    float tv0 = t[3 * f + 0];
    float tv1 = t[3 * f + 1];
    float tv2 = t[3 * f + 2];

    float Inv[3][4];
#pragma unroll
    for (int i = 0; i < 3; i++) {
        Inv[i][0] = R[0][i];
        Inv[i][1] = R[1][i];
        Inv[i][2] = R[2][i];
        Inv[i][3] = -(R[0][i] * tv0 + R[1][i] * tv1 + R[2][i] * tv2);
    }

    // Only rows 0..2 are consumed by the gather (row 3 == (0,0,0,1) always).
    const float4* E0 = (const float4*)(E + 16 * f);
#pragma unroll
    for (int i = 0; i < 3; i++) {
        float4 e = E0[i];
        float4 row;
        row.x = e.x * Inv[0][0] + e.y * Inv[1][0] + e.z * Inv[2][0];
        row.y = e.x * Inv[0][1] + e.y * Inv[1][1] + e.z * Inv[2][1];
        row.z = e.x * Inv[0][2] + e.y * Inv[1][2] + e.z * Inv[2][2];
        row.w = e.x * Inv[0][3] + e.y * Inv[1][3] + e.z * Inv[2][3] + e.w;
        g_M[f * 4 + i] = row;
    }
}

// ---------------------------------------------------------------------------
// Phase 2: gather. Quad-lane layout; the q==3 lane of each ray stores the
// constant (0,0,0,1) WITHOUT any table read -> the warp's table LDG touches
// 6 random lines instead of 8 (-25% L1 replay work, -32MB L2 reads).
// ---------------------------------------------------------------------------
#define GATHER_ILP 4
__global__ void __launch_bounds__(256) gather_kernel(
        const int* __restrict__ cam,
        float4* __restrict__ out,
        int n_chunks, int nf) {
    int base = blockIdx.x * (blockDim.x * GATHER_ILP) + threadIdx.x;
    const float4 bottom = make_float4(0.0f, 0.0f, 0.0f, 1.0f);

    if (base + (GATHER_ILP - 1) * blockDim.x < n_chunks) {
        float4 v[GATHER_ILP];
#pragma unroll
        for (int k = 0; k < GATHER_ILP; k++) {
            int c = base + k * blockDim.x;
            int ray = c >> 2;
            int q   = c & 3;
            if (q == 3) {
                v[k] = bottom;                     // row 3 is constant: no load
            } else {
                int f = __ldg(&cam[ray]);
                f = min(max(f, 0), nf - 1);
                v[k] = __ldg(&g_M[f * 4 + q]);
            }
        }
#pragma unroll
        for (int k = 0; k < GATHER_ILP; k++)
            out[base + k * blockDim.x] = v[k];
    } else {
#pragma unroll
        for (int k = 0; k < GATHER_ILP; k++) {
            int c = base + k * blockDim.x;
            if (c < n_chunks) {
                int ray = c >> 2;
                int q   = c & 3;
                if (q == 3) {
                    out[c] = bottom;
                } else {
                    int f = __ldg(&cam[ray]);
                    f = min(max(f, 0), nf - 1);
                    out[c] = __ldg(&g_M[f * 4 + q]);
                }
            }
        }
    }
}

extern "C" void kernel_launch(void* const* d_in, const int* in_sizes, int n_in,
                              void* d_out, int out_size) {
    const float* r   = (const float*)d_in[0];   // (NF, 3)
    const float* t   = (const float*)d_in[1];   // (NF, 3)
    const float* E   = (const float*)d_in[2];   // (NF, 4, 4)
    const int*   cam = (const int*)d_in[3];     // (NR,) int32

    int nf = in_sizes[0] / 3;
    if (nf > NF_MAX) nf = NF_MAX;
    int nr = in_sizes[3];

    precompute_kernel<<<(nf + 63) / 64, 64>>>(r, t, E, nf);

    int n_chunks = nr * 4;
    int threads = 256;
    int per_block = threads * GATHER_ILP;
    int grid = (n_chunks + per_block - 1) / per_block;
    gather_kernel<<<grid, threads>>>(cam, (float4*)d_out, n_chunks, nf);
}